// round 13
// baseline (speedup 1.0000x reference)
#include <cuda_runtime.h>
#include <cuda_fp16.h>
#include <cstdint>

// ComplexBlockLinear, mma.sync fp16 m16n8k16. Round 13 (R10 base):
//  - W pre-converted to planar f16; B frags via ONE ldmatrix.x4.trans per
//    (s,nt) with lane-split planes (verified in R12).
//  - X staged f32 via cp.async.cg (bypass L1; no reuse), R10 XOR layout.
//  - single __syncthreads per chunk (wait -> sync -> issue -> compute).
// CTA = 64 rows x 1 block, 8 warps (2M x 4N), warp tile 32x32, KC=32,
// 256 thr, 2 CTAs/SM.

#define NBLK 8
#define BS 128
#define HD 1024
#define CTA_M 64
#define KC 32
#define NCHUNK (BS / KC)     // 4
#define THREADS 256

// per-stage smem:
//   XR/XI: 2 k16-halves x 64 rows x 16 f32, XOR-group swizzle   8192 B each
//   WR/WI: 32 k-rows x 272 B (128 f16 + 8 pad)                  8704 B each
#define XR_OFF 0
#define XI_OFF 8192
#define WR_OFF 16384
#define WI_OFF 25088
#define STAGE_BYTES 33792
#define SMEM_TOTAL (2 * STAGE_BYTES)   // 67584
#define WROWB 272

// pre-converted weight planes, [nblk*128 k][128 n] f16
__device__ __align__(16) __half g_wre[NBLK * BS * BS];
__device__ __align__(16) __half g_wim[NBLK * BS * BS];

__device__ __forceinline__ uint32_t smem_u32(const void* p) {
    uint32_t a;
    asm("{ .reg .u64 t; cvta.to.shared.u64 t, %1; cvt.u32.u64 %0, t; }"
        : "=r"(a) : "l"(p));
    return a;
}
__device__ __forceinline__ unsigned pack_h2(float lo, float hi) {
    unsigned d;
    asm("cvt.rn.f16x2.f32 %0, %1, %2;" : "=r"(d) : "f"(hi), "f"(lo));
    return d;
}
__device__ __forceinline__ void cp16_ca(uint32_t dst, const void* src) {
    asm volatile("cp.async.ca.shared.global [%0], [%1], 16;"
                 :: "r"(dst), "l"(src) : "memory");
}
__device__ __forceinline__ void cp16_cg(uint32_t dst, const void* src) {
    asm volatile("cp.async.cg.shared.global [%0], [%1], 16;"
                 :: "r"(dst), "l"(src) : "memory");
}
__device__ __forceinline__ void cp_commit() {
    asm volatile("cp.async.commit_group;" ::: "memory");
}
template <int N>
__device__ __forceinline__ void cp_wait() {
    asm volatile("cp.async.wait_group %0;" :: "n"(N) : "memory");
}
// x4.trans: r0,r1 = k-lo/k-hi of plane addressed by lanes 0-15;
//           r2,r3 = plane addressed by lanes 16-31.
__device__ __forceinline__ void ldsm_x4t(unsigned& r0, unsigned& r1,
                                         unsigned& r2, unsigned& r3,
                                         uint32_t addr) {
    asm volatile(
        "ldmatrix.sync.aligned.m8n8.x4.trans.shared.b16 {%0,%1,%2,%3},[%4];"
        : "=r"(r0), "=r"(r1), "=r"(r2), "=r"(r3) : "r"(addr));
}
__device__ __forceinline__ void mma_f16(float* d, const unsigned* a,
                                        unsigned b0, unsigned b1) {
    asm volatile(
        "mma.sync.aligned.m16n8k16.row.col.f32.f16.f16.f32 "
        "{%0,%1,%2,%3},{%4,%5,%6,%7},{%8,%9},{%0,%1,%2,%3};\n"
        : "+f"(d[0]), "+f"(d[1]), "+f"(d[2]), "+f"(d[3])
        : "r"(a[0]), "r"(a[1]), "r"(a[2]), "r"(a[3]), "r"(b0), "r"(b1));
}

// ---- weight conversion: [8,128,128,2] f32 -> planar f16 ----
__global__ void wconv_kernel(const float* __restrict__ w) {
    const int idx = blockIdx.x * 256 + threadIdx.x;   // 0..131071
    const float2 v = ((const float2*)w)[idx];
    g_wre[idx] = __float2half_rn(v.x);
    g_wim[idx] = __float2half_rn(v.y);
}

__global__ __launch_bounds__(THREADS, 2)
void cbl_h16f_kernel(const float* __restrict__ xre,
                     const float* __restrict__ xim,
                     float* __restrict__ out) {
    extern __shared__ char smem[];
    const uint32_t sb = smem_u32(smem);

    const int tid  = threadIdx.x;
    const int lane = tid & 31;
    const int warp = tid >> 5;
    const int wm   = warp >> 2;    // 0..1
    const int wn   = warp & 3;     // 0..3

    const int row0 = blockIdx.x * CTA_M;
    const int nb   = blockIdx.y;

    float accR[2][4][4], accI[2][4][4];
#pragma unroll
    for (int a = 0; a < 2; a++)
#pragma unroll
        for (int b = 0; b < 4; b++)
#pragma unroll
            for (int c = 0; c < 4; c++) { accR[a][b][c] = 0.f; accI[a][b][c] = 0.f; }

    auto issue = [&](int c) {
        const uint32_t base = sb + (c & 1) * STAGE_BYTES;
        const int k0 = c * KC;
        // X (.cg, no L1): 2 arrays x 2 halves x 64 rows x 4 groups = 1024, 4/thr
#pragma unroll
        for (int q = 0; q < 4; ++q) {
            const int e   = q * THREADS + tid;     // 0..1023
            const int arr = e >> 9;                // 0: re, 1: im
            const int s   = (e >> 8) & 1;          // k16 half
            const int r   = (e >> 2) & 63;
            const int t   = e & 3;
            const float* src = (arr ? xim : xre) +
                (size_t)(row0 + r) * HD + nb * BS + k0 + s * 16 + t * 4;
            const uint32_t doff = ((s * 64 + r) * 16 + ((t ^ (r & 3)) * 4)) * 4;
            cp16_cg(base + (arr ? XI_OFF : XR_OFF) + doff, src);
        }
        // W f16 (.ca, reused across 512 row-tiles): 1024 chunks, 4/thread
#pragma unroll
        for (int q = 0; q < 4; ++q) {
            const int e   = q * THREADS + tid;     // 0..1023
            const int arr = e >> 9;
            const int kk  = (e >> 4) & 31;
            const int c16 = e & 15;
            const __half* src = (arr ? g_wim : g_wre) +
                (size_t)(nb * BS + k0 + kk) * BS + c16 * 8;
            cp16_ca(base + (arr ? WI_OFF : WR_OFF) + kk * WROWB + c16 * 16, src);
        }
        cp_commit();
    };

    issue(0);

    const int g = lane >> 2;
    const int t = lane & 3;
    // ldmatrix.x4 lane base: lanes 0-15 -> WR, 16-31 -> WI; k-lo/k-hi by bit3
    const uint32_t ldsm_kr   = (uint32_t)((lane & 7) + ((lane >> 3) & 1) * 8);
    const uint32_t ldsm_base = ((lane & 16) ? WI_OFF : WR_OFF) + ldsm_kr * WROWB;

#pragma unroll 1
    for (int c = 0; c < NCHUNK; ++c) {
        cp_wait<0>();          // group c complete (only pending group)
        __syncthreads();       // publish stage c; retire stage c-1 readers
        if (c + 1 < NCHUNK) issue(c + 1);   // overwrites buffer (c+1)&1 safely

        const uint32_t base = sb + (c & 1) * STAGE_BYTES;
        const float* sXR = (const float*)(smem + (c & 1) * STAGE_BYTES + XR_OFF);
        const float* sXI = (const float*)(smem + (c & 1) * STAGE_BYTES + XI_OFF);

#pragma unroll
        for (int s = 0; s < 2; ++s) {     // two k16 steps per chunk
            // ---- A fragments from f32 X smem (R10 path)
            unsigned ar[2][4], ai[2][4];
#pragma unroll
            for (int mt = 0; mt < 2; ++mt) {
                const int rr = s * 64 + wm * 32 + mt * 16 + g;
                const int sz = rr & 3;
                const int c_lo = (((t >> 1) ^ sz) << 2) + (2 * t & 2);
                const int c_hi = ((((t >> 1) + 2) ^ sz) << 2) + (2 * t & 2);
                float2 v;
                v = *(const float2*)&sXR[rr * 16 + c_lo];
                ar[mt][0] = pack_h2(v.x, v.y);
                v = *(const float2*)&sXR[(rr + 8) * 16 + c_lo];
                ar[mt][1] = pack_h2(v.x, v.y);
                v = *(const float2*)&sXR[rr * 16 + c_hi];
                ar[mt][2] = pack_h2(v.x, v.y);
                v = *(const float2*)&sXR[(rr + 8) * 16 + c_hi];
                ar[mt][3] = pack_h2(v.x, v.y);
                v = *(const float2*)&sXI[rr * 16 + c_lo];
                ai[mt][0] = pack_h2(v.x, v.y);
                v = *(const float2*)&sXI[(rr + 8) * 16 + c_lo];
                ai[mt][1] = pack_h2(v.x, v.y);
                v = *(const float2*)&sXI[rr * 16 + c_hi];
                ai[mt][2] = pack_h2(v.x, v.y);
                v = *(const float2*)&sXI[(rr + 8) * 16 + c_hi];
                ai[mt][3] = pack_h2(v.x, v.y);
            }

            // ---- B fragments: one ldmatrix.x4.trans per n-tile (re+im)
            const uint32_t krow = base + ldsm_base + (uint32_t)(s * 16) * WROWB;
#pragma unroll
            for (int nt = 0; nt < 4; ++nt) {
                const uint32_t ncol = (uint32_t)(wn * 32 + nt * 8) * 2;
                unsigned bR0, bR1, bI0, bI1;
                ldsm_x4t(bR0, bR1, bI0, bI1, krow + ncol);
                const unsigned nI0 = bI0 ^ 0x80008000u;
                const unsigned nI1 = bI1 ^ 0x80008000u;
#pragma unroll
                for (int mt = 0; mt < 2; ++mt) {
                    mma_f16(accR[mt][nt], ar[mt], bR0, bR1);
                    mma_f16(accR[mt][nt], ai[mt], nI0, nI1);
                    mma_f16(accI[mt][nt], ar[mt], bI0, bI1);
                    mma_f16(accI[mt][nt], ai[mt], bR0, bR1);
                }
            }
        }
    }

    // ---- epilogue: interleave (re,im) -> float4 stores, view_as_real layout
#pragma unroll
    for (int mt = 0; mt < 2; ++mt) {
        const int r_lo = row0 + wm * 32 + mt * 16 + (lane >> 2);
#pragma unroll
        for (int nt = 0; nt < 4; ++nt) {
            const int col = nb * BS + wn * 32 + nt * 8 + (lane & 3) * 2;
            float4 v0 = make_float4(accR[mt][nt][0], accI[mt][nt][0],
                                    accR[mt][nt][1], accI[mt][nt][1]);
            float4 v1 = make_float4(accR[mt][nt][2], accI[mt][nt][2],
                                    accR[mt][nt][3], accI[mt][nt][3]);
            *(float4*)(out + ((size_t)r_lo * HD + col) * 2)       = v0;
            *(float4*)(out + ((size_t)(r_lo + 8) * HD + col) * 2) = v1;
        }
    }
}

extern "C" void kernel_launch(void* const* d_in, const int* in_sizes, int n_in,
                              void* d_out, int out_size) {
    const float* xre = (const float*)d_in[0];
    const float* xim = (const float*)d_in[1];
    const float* w   = (const float*)d_in[2];
    float* out       = (float*)d_out;

    wconv_kernel<<<NBLK * BS * BS / 256, 256>>>(w);

    cudaFuncSetAttribute(cbl_h16f_kernel,
                         cudaFuncAttributeMaxDynamicSharedMemorySize, SMEM_TOTAL);
    dim3 grid(32768 / CTA_M, NBLK);   // (512, 8)
    cbl_h16f_kernel<<<grid, THREADS, SMEM_TOTAL>>>(xre, xim, out);
}

// round 14
// speedup vs baseline: 1.3343x; 1.3343x over previous
#include <cuda_runtime.h>
#include <cuda_fp16.h>
#include <cstdint>

// ComplexBlockLinear, mma.sync fp16 m16n8k16. Round 14 = Round 10 (141.3us)
// with exactly ONE change: B fragments via ldmatrix.x4.trans (lane-split
// planes), halving B-side smem instructions. Everything else identical.
// CTA = 64 rows x 1 block, 8 warps (2M x 4N), warp tile 32x32, KC=32,
// 256 thr, 2 CTAs/SM, 2-stage cp.async (.ca), two syncs per chunk.

#define NBLK 8
#define BS 128
#define HD 1024
#define CTA_M 64
#define KC 32
#define NCHUNK (BS / KC)     // 4
#define THREADS 256

// per-stage smem:
//   XR/XI: 2 k16-halves x 64 rows x 16 f32, XOR-group swizzle   8192 B each
//   WR/WI: 32 k-rows x 272 B (128 f16 + 8 pad)                  8704 B each
#define XR_OFF 0
#define XI_OFF 8192
#define WR_OFF 16384
#define WI_OFF 25088
#define STAGE_BYTES 33792
#define SMEM_TOTAL (2 * STAGE_BYTES)   // 67584
#define WROWB 272

// pre-converted weight planes, [nblk*128 k][128 n] f16
__device__ __align__(16) __half g_wre[NBLK * BS * BS];
__device__ __align__(16) __half g_wim[NBLK * BS * BS];

__device__ __forceinline__ uint32_t smem_u32(const void* p) {
    uint32_t a;
    asm("{ .reg .u64 t; cvta.to.shared.u64 t, %1; cvt.u32.u64 %0, t; }"
        : "=r"(a) : "l"(p));
    return a;
}
__device__ __forceinline__ unsigned pack_h2(float lo, float hi) {
    unsigned d;
    asm("cvt.rn.f16x2.f32 %0, %1, %2;" : "=r"(d) : "f"(hi), "f"(lo));
    return d;
}
__device__ __forceinline__ void cp16(uint32_t dst, const void* src) {
    asm volatile("cp.async.ca.shared.global [%0], [%1], 16;"
                 :: "r"(dst), "l"(src) : "memory");
}
__device__ __forceinline__ void cp_commit() {
    asm volatile("cp.async.commit_group;" ::: "memory");
}
template <int N>
__device__ __forceinline__ void cp_wait() {
    asm volatile("cp.async.wait_group %0;" :: "n"(N) : "memory");
}
// x4.trans: r0,r1 = k-lo/k-hi of plane addressed by lanes 0-15;
//           r2,r3 = plane addressed by lanes 16-31.
__device__ __forceinline__ void ldsm_x4t(unsigned& r0, unsigned& r1,
                                         unsigned& r2, unsigned& r3,
                                         uint32_t addr) {
    asm volatile(
        "ldmatrix.sync.aligned.m8n8.x4.trans.shared.b16 {%0,%1,%2,%3},[%4];"
        : "=r"(r0), "=r"(r1), "=r"(r2), "=r"(r3) : "r"(addr));
}
__device__ __forceinline__ void mma_f16(float* d, const unsigned* a,
                                        unsigned b0, unsigned b1) {
    asm volatile(
        "mma.sync.aligned.m16n8k16.row.col.f32.f16.f16.f32 "
        "{%0,%1,%2,%3},{%4,%5,%6,%7},{%8,%9},{%0,%1,%2,%3};\n"
        : "+f"(d[0]), "+f"(d[1]), "+f"(d[2]), "+f"(d[3])
        : "r"(a[0]), "r"(a[1]), "r"(a[2]), "r"(a[3]), "r"(b0), "r"(b1));
}

// ---- weight conversion: [8,128,128,2] f32 -> planar f16 ----
__global__ void wconv_kernel(const float* __restrict__ w) {
    const int idx = blockIdx.x * 256 + threadIdx.x;   // 0..131071
    const float2 v = ((const float2*)w)[idx];
    g_wre[idx] = __float2half_rn(v.x);
    g_wim[idx] = __float2half_rn(v.y);
}

__global__ __launch_bounds__(THREADS, 2)
void cbl_h16v_kernel(const float* __restrict__ xre,
                     const float* __restrict__ xim,
                     float* __restrict__ out) {
    extern __shared__ char smem[];
    const uint32_t sb = smem_u32(smem);

    const int tid  = threadIdx.x;
    const int lane = tid & 31;
    const int warp = tid >> 5;
    const int wm   = warp >> 2;    // 0..1
    const int wn   = warp & 3;     // 0..3

    const int row0 = blockIdx.x * CTA_M;
    const int nb   = blockIdx.y;

    float accR[2][4][4], accI[2][4][4];
#pragma unroll
    for (int a = 0; a < 2; a++)
#pragma unroll
        for (int b = 0; b < 4; b++)
#pragma unroll
            for (int c = 0; c < 4; c++) { accR[a][b][c] = 0.f; accI[a][b][c] = 0.f; }

    auto issue = [&](int c) {
        const uint32_t base = sb + (c & 1) * STAGE_BYTES;
        const int k0 = c * KC;
        // X: 2 arrays x 2 halves x 64 rows x 4 groups = 1024 chunks, 4/thread
#pragma unroll
        for (int q = 0; q < 4; ++q) {
            const int e   = q * THREADS + tid;     // 0..1023
            const int arr = e >> 9;                // 0: re, 1: im
            const int s   = (e >> 8) & 1;          // k16 half
            const int r   = (e >> 2) & 63;
            const int t   = e & 3;
            const float* src = (arr ? xim : xre) +
                (size_t)(row0 + r) * HD + nb * BS + k0 + s * 16 + t * 4;
            const uint32_t doff = ((s * 64 + r) * 16 + ((t ^ (r & 3)) * 4)) * 4;
            cp16(base + (arr ? XI_OFF : XR_OFF) + doff, src);
        }
        // W f16: 2 arrays x 32 k-rows x 16 chunks (16B = 8 f16) = 1024, 4/thread
#pragma unroll
        for (int q = 0; q < 4; ++q) {
            const int e   = q * THREADS + tid;     // 0..1023
            const int arr = e >> 9;
            const int kk  = (e >> 4) & 31;
            const int c16 = e & 15;
            const __half* src = (arr ? g_wim : g_wre) +
                (size_t)(nb * BS + k0 + kk) * BS + c16 * 8;
            cp16(base + (arr ? WI_OFF : WR_OFF) + kk * WROWB + c16 * 16, src);
        }
        cp_commit();
    };

    issue(0);

    const int g = lane >> 2;
    const int t = lane & 3;
    // ldmatrix.x4 lane base: lanes 0-15 -> WR, 16-31 -> WI; k-lo/k-hi by bit3
    const uint32_t ldsm_kr   = (uint32_t)((lane & 7) + ((lane >> 3) & 1) * 8);
    const uint32_t ldsm_base = ((lane & 16) ? WI_OFF : WR_OFF) + ldsm_kr * WROWB;

#pragma unroll 1
    for (int c = 0; c < NCHUNK; ++c) {
        if (c + 1 < NCHUNK) { issue(c + 1); cp_wait<1>(); }
        else                { cp_wait<0>(); }
        __syncthreads();

        const uint32_t base = sb + (c & 1) * STAGE_BYTES;
        const float* sXR = (const float*)(smem + (c & 1) * STAGE_BYTES + XR_OFF);
        const float* sXI = (const float*)(smem + (c & 1) * STAGE_BYTES + XI_OFF);

#pragma unroll
        for (int s = 0; s < 2; ++s) {     // two k16 steps per chunk
            // ---- A fragments from f32 X smem (R10 path)
            unsigned ar[2][4], ai[2][4];
#pragma unroll
            for (int mt = 0; mt < 2; ++mt) {
                const int rr = s * 64 + wm * 32 + mt * 16 + g;
                const int sz = rr & 3;
                const int c_lo = (((t >> 1) ^ sz) << 2) + (2 * t & 2);
                const int c_hi = ((((t >> 1) + 2) ^ sz) << 2) + (2 * t & 2);
                float2 v;
                v = *(const float2*)&sXR[rr * 16 + c_lo];
                ar[mt][0] = pack_h2(v.x, v.y);
                v = *(const float2*)&sXR[(rr + 8) * 16 + c_lo];
                ar[mt][1] = pack_h2(v.x, v.y);
                v = *(const float2*)&sXR[rr * 16 + c_hi];
                ar[mt][2] = pack_h2(v.x, v.y);
                v = *(const float2*)&sXR[(rr + 8) * 16 + c_hi];
                ar[mt][3] = pack_h2(v.x, v.y);
                v = *(const float2*)&sXI[rr * 16 + c_lo];
                ai[mt][0] = pack_h2(v.x, v.y);
                v = *(const float2*)&sXI[(rr + 8) * 16 + c_lo];
                ai[mt][1] = pack_h2(v.x, v.y);
                v = *(const float2*)&sXI[rr * 16 + c_hi];
                ai[mt][2] = pack_h2(v.x, v.y);
                v = *(const float2*)&sXI[(rr + 8) * 16 + c_hi];
                ai[mt][3] = pack_h2(v.x, v.y);
            }

            // ---- B fragments: one ldmatrix.x4.trans per n-tile (re+im)
            const uint32_t krow = base + ldsm_base + (uint32_t)(s * 16) * WROWB;
#pragma unroll
            for (int nt = 0; nt < 4; ++nt) {
                const uint32_t ncol = (uint32_t)(wn * 32 + nt * 8) * 2;
                unsigned bR0, bR1, bI0, bI1;
                ldsm_x4t(bR0, bR1, bI0, bI1, krow + ncol);
                const unsigned nI0 = bI0 ^ 0x80008000u;
                const unsigned nI1 = bI1 ^ 0x80008000u;
#pragma unroll
                for (int mt = 0; mt < 2; ++mt) {
                    mma_f16(accR[mt][nt], ar[mt], bR0, bR1);
                    mma_f16(accR[mt][nt], ai[mt], nI0, nI1);
                    mma_f16(accI[mt][nt], ar[mt], bI0, bI1);
                    mma_f16(accI[mt][nt], ai[mt], bR0, bR1);
                }
            }
        }
        __syncthreads();   // buffer free for stage c+2
    }

    // ---- epilogue: interleave (re,im) -> float4 stores, view_as_real layout
#pragma unroll
    for (int mt = 0; mt < 2; ++mt) {
        const int r_lo = row0 + wm * 32 + mt * 16 + (lane >> 2);
#pragma unroll
        for (int nt = 0; nt < 4; ++nt) {
            const int col = nb * BS + wn * 32 + nt * 8 + (lane & 3) * 2;
            float4 v0 = make_float4(accR[mt][nt][0], accI[mt][nt][0],
                                    accR[mt][nt][1], accI[mt][nt][1]);
            float4 v1 = make_float4(accR[mt][nt][2], accI[mt][nt][2],
                                    accR[mt][nt][3], accI[mt][nt][3]);
            *(float4*)(out + ((size_t)r_lo * HD + col) * 2)       = v0;
            *(float4*)(out + ((size_t)(r_lo + 8) * HD + col) * 2) = v1;
        }
    }
}

extern "C" void kernel_launch(void* const* d_in, const int* in_sizes, int n_in,
                              void* d_out, int out_size) {
    const float* xre = (const float*)d_in[0];
    const float* xim = (const float*)d_in[1];
    const float* w   = (const float*)d_in[2];
    float* out       = (float*)d_out;

    wconv_kernel<<<NBLK * BS * BS / 256, 256>>>(w);

    cudaFuncSetAttribute(cbl_h16v_kernel,
                         cudaFuncAttributeMaxDynamicSharedMemorySize, SMEM_TOTAL);
    dim3 grid(32768 / CTA_M, NBLK);   // (512, 8)
    cbl_h16v_kernel<<<grid, THREADS, SMEM_TOTAL>>>(xre, xim, out);
}